// round 9
// baseline (speedup 1.0000x reference)
#include <cuda_runtime.h>
#include <cstdint>

// Problem constants
#define Bn 4
#define Cn 32
#define Ln 256
#define Mn 256
#define Fn 8
#define Nn 64
#define FC (Fn * Cn)          // 256
#define LM (Ln * Mn)          // 65536
#define IMAG_OFF ((size_t)Bn * Fn * LM)  // 2,097,152
#define CB 4                  // c-batch size (front-batched LDG.128)

union U64 {
    unsigned long long u;
    float2 f;
};

__device__ __forceinline__ unsigned long long ffma2(unsigned long long a,
                                                    unsigned long long b,
                                                    unsigned long long c) {
    unsigned long long d;
    asm("fma.rn.f32x2 %0, %1, %2, %3;" : "=l"(d) : "l"(a), "l"(b), "l"(c));
    return d;
}

// ---------------------------------------------------------------------------
// Grid: B*L = 1024 blocks, 64 threads. Block = one (b, l).
// Thread t: 4 consecutive m via LDG.128 (ulonglong2), all 8 f.
// c-loop: 8 batches of 4 c, each front-batching 8 LDG.128 (4 KB/warp burst).
// 9 blocks/SM (reg cap ~112) -> single wave, 18 warps/SM.
// ---------------------------------------------------------------------------
__global__ __launch_bounds__(64, 9) void sphere_v9_kernel(
    const float* __restrict__ xr,
    const float* __restrict__ xi,
    const float* __restrict__ wr,
    const float* __restrict__ wi,
    float* __restrict__ out) {
    __shared__ ulonglong2 s2[FC];   // 4 KB: { {wr,wr}, {wi,wi} } per (f,c)

    int bid = blockIdx.x;
    int b = bid >> 8;
    int l = bid & (Ln - 1);
    int tid = threadIdx.x;

    // --- interpolate this l's weights into shared (4 entries/thread) ---
    {
        float t = (float)l * (63.0f / 255.0f);
        int lo = (int)t;
        if (lo > Nn - 2) lo = Nn - 2;
        float fr = t - (float)lo;
        float om = 1.0f - fr;
#pragma unroll
        for (int j = 0; j < 4; ++j) {
            int k = tid + j * 64;
            const float* pwr = wr + k * Nn + lo;
            const float* pwi = wi + k * Nn + lo;
            float vr = pwr[0] * om + pwr[1] * fr;
            float vi = pwi[0] * om + pwi[1] * fr;
            U64 ur, ui;
            ur.f = make_float2(vr, vr);
            ui.f = make_float2(vi, vi);
            s2[k] = make_ulonglong2(ur.u, ui.u);
        }
    }
    __syncthreads();

    int m0 = tid * 4;
    const ulonglong2* pr = reinterpret_cast<const ulonglong2*>(
        xr + (size_t)b * Cn * LM + (size_t)l * Mn + m0);
    const ulonglong2* pi = reinterpret_cast<const ulonglong2*>(
        xi + (size_t)b * Cn * LM + (size_t)l * Mn + m0);
    const int step = LM / 4;   // ulonglong2 stride per c (byte offset fits imm24)

    // accumulators: 8 f x (re, im) x 2 u64 (4 m) = 32 u64
    unsigned long long ar[Fn][2], ai[Fn][2];
#pragma unroll
    for (int f = 0; f < Fn; ++f) {
        ar[f][0] = 0ull; ar[f][1] = 0ull;
        ai[f][0] = 0ull; ai[f][1] = 0ull;
    }

    const unsigned long long SMSK = 0x8000000080000000ULL;

#pragma unroll
    for (int cb = 0; cb < Cn; cb += CB) {
        // ---- front-batched loads: 8 LDG.128 with constant offsets ----
        ulonglong2 xrv[CB], xiv[CB];
#pragma unroll
        for (int j = 0; j < CB; ++j) {
            xrv[j] = __ldg(pr + j * step);
            xiv[j] = __ldg(pi + j * step);
        }
        pr += CB * step;
        pi += CB * step;

        // ---- compute over the batch ----
#pragma unroll
        for (int j = 0; j < CB; ++j) {
            int c = cb + j;
            unsigned long long xr01 = xrv[j].x, xr23 = xrv[j].y;
            unsigned long long xi01 = xiv[j].x, xi23 = xiv[j].y;
            unsigned long long nx01 = xi01 ^ SMSK, nx23 = xi23 ^ SMSK;
#pragma unroll
            for (int f = 0; f < Fn; ++f) {
                ulonglong2 w = s2[f * Cn + c];   // broadcast LDS.128
                ar[f][0] = ffma2(w.x, xr01, ar[f][0]);
                ar[f][0] = ffma2(w.y, nx01, ar[f][0]);
                ar[f][1] = ffma2(w.x, xr23, ar[f][1]);
                ar[f][1] = ffma2(w.y, nx23, ar[f][1]);
                ai[f][0] = ffma2(w.x, xi01, ai[f][0]);
                ai[f][0] = ffma2(w.y, xr01, ai[f][0]);
                ai[f][1] = ffma2(w.x, xi23, ai[f][1]);
                ai[f][1] = ffma2(w.y, xr23, ai[f][1]);
            }
        }
    }

    float sc = sqrtf(1.0f + (float)l) * (1.0f / 32.0f);
    float* o_real = out + (size_t)b * Fn * LM + (size_t)l * Mn + m0;
    float* o_imag = o_real + IMAG_OFF;

#pragma unroll
    for (int f = 0; f < Fn; ++f) {
        U64 u0, u1;
        u0.u = ar[f][0]; u1.u = ar[f][1];
        float4 vr4;
        vr4.x = fmaxf(u0.f.x * sc, 0.0f);
        vr4.y = fmaxf(u0.f.y * sc, 0.0f);
        vr4.z = fmaxf(u1.f.x * sc, 0.0f);
        vr4.w = fmaxf(u1.f.y * sc, 0.0f);
        *reinterpret_cast<float4*>(o_real + (size_t)f * LM) = vr4;

        u0.u = ai[f][0]; u1.u = ai[f][1];
        float4 vi4;
        vi4.x = u0.f.x * sc;
        vi4.y = u0.f.y * sc;
        vi4.z = u1.f.x * sc;
        vi4.w = u1.f.y * sc;
        *reinterpret_cast<float4*>(o_imag + (size_t)f * LM) = vi4;
    }
}

extern "C" void kernel_launch(void* const* d_in, const int* in_sizes, int n_in,
                              void* d_out, int out_size) {
    const float* x_real = (const float*)d_in[0];
    const float* x_imag = (const float*)d_in[1];
    const float* w_real = (const float*)d_in[2];
    const float* w_imag = (const float*)d_in[3];
    float* out = (float*)d_out;

    sphere_v9_kernel<<<Bn * Ln, 64>>>(x_real, x_imag, w_real, w_imag, out);
}

// round 11
// speedup vs baseline: 1.1969x; 1.1969x over previous
#include <cuda_runtime.h>
#include <cstdint>

// Problem constants
#define Bn 4
#define Cn 32
#define Ln 256
#define Mn 256
#define Fn 8
#define Nn 64
#define FC (Fn * Cn)          // 256
#define LM (Ln * Mn)          // 65536
#define IMAG_OFF ((size_t)Bn * Fn * LM)  // 2,097,152
#define CB 4                  // c per batch
#define NB (Cn / CB)          // 8 batches

union U64 {
    unsigned long long u;
    float2 f;
};

__device__ __forceinline__ unsigned long long ffma2(unsigned long long a,
                                                    unsigned long long b,
                                                    unsigned long long c) {
    unsigned long long d;
    asm("fma.rn.f32x2 %0, %1, %2, %3;" : "=l"(d) : "l"(a), "l"(b), "l"(c));
    return d;
}

// ---------------------------------------------------------------------------
// Grid: B*L = 1024 blocks, 128 threads. Block = one (b, l).
// Thread t: m-pair t (2 consecutive m), all 8 f.
// Software-pipelined c-loop: double-buffered batches of 4 c; batch t+1's
// 8 LDG.64 issue BEFORE batch t's compute, so DRAM latency is covered by a
// full batch of FFMA work. Single base pointer, constant imm offsets.
// ---------------------------------------------------------------------------
__global__ __launch_bounds__(128, 6) void sphere_v10_kernel(
    const float* __restrict__ xr,
    const float* __restrict__ xi,
    const float* __restrict__ wr,
    const float* __restrict__ wi,
    float* __restrict__ out) {
    __shared__ ulonglong2 s2[FC];   // 4 KB: { {wr,wr}, {wi,wi} } per (f,c)

    int bid = blockIdx.x;
    int b = bid >> 8;
    int l = bid & (Ln - 1);
    int tid = threadIdx.x;

    // --- interpolate this l's weights into shared ---
    {
        float t = (float)l * (63.0f / 255.0f);
        int lo = (int)t;
        if (lo > Nn - 2) lo = Nn - 2;
        float fr = t - (float)lo;
        float om = 1.0f - fr;
#pragma unroll
        for (int j = 0; j < 2; ++j) {
            int k = tid + j * 128;
            const float* pwr = wr + k * Nn + lo;
            const float* pwi = wi + k * Nn + lo;
            float vr = pwr[0] * om + pwr[1] * fr;
            float vi = pwi[0] * om + pwi[1] * fr;
            U64 ur, ui;
            ur.f = make_float2(vr, vr);
            ui.f = make_float2(vi, vi);
            s2[k] = make_ulonglong2(ur.u, ui.u);
        }
    }
    __syncthreads();

    int m0 = tid * 2;
    const unsigned long long* pr = reinterpret_cast<const unsigned long long*>(
        xr + (size_t)b * Cn * LM + (size_t)l * Mn + m0);
    const unsigned long long* pi = reinterpret_cast<const unsigned long long*>(
        xi + (size_t)b * Cn * LM + (size_t)l * Mn + m0);
    const int step = LM / 2;   // u64 per c; max byte offset 31*256KB < 8MB imm

    unsigned long long ar[Fn], ai[Fn];
#pragma unroll
    for (int f = 0; f < Fn; ++f) { ar[f] = 0ull; ai[f] = 0ull; }

    const unsigned long long SMSK = 0x8000000080000000ULL;

    // double-buffered register batches
    unsigned long long bufR[2][CB], bufI[2][CB];

    // prologue: load batch 0
#pragma unroll
    for (int j = 0; j < CB; ++j) {
        bufR[0][j] = __ldg(pr + j * step);
        bufI[0][j] = __ldg(pi + j * step);
    }

#pragma unroll
    for (int t = 0; t < NB; ++t) {
        const int cur = t & 1;
        const int nxt = cur ^ 1;

        // issue next batch's loads FIRST (prefetch distance = 1 batch)
        if (t + 1 < NB) {
#pragma unroll
            for (int j = 0; j < CB; ++j) {
                bufR[nxt][j] = __ldg(pr + ((t + 1) * CB + j) * step);
                bufI[nxt][j] = __ldg(pi + ((t + 1) * CB + j) * step);
            }
        }

        // compute current batch
#pragma unroll
        for (int j = 0; j < CB; ++j) {
            int c = t * CB + j;
            unsigned long long xrc = bufR[cur][j];
            unsigned long long xic = bufI[cur][j];
            unsigned long long nxi = xic ^ SMSK;
#pragma unroll
            for (int f = 0; f < Fn; ++f) {
                ulonglong2 w = s2[f * Cn + c];   // broadcast LDS.128
                ar[f] = ffma2(w.x, xrc, ar[f]);
                ar[f] = ffma2(w.y, nxi, ar[f]);
                ai[f] = ffma2(w.x, xic, ai[f]);
                ai[f] = ffma2(w.y, xrc, ai[f]);
            }
        }
    }

    float sc = sqrtf(1.0f + (float)l) * (1.0f / 32.0f);
    float* o_real = out + (size_t)b * Fn * LM + (size_t)l * Mn + m0;
    float* o_imag = o_real + IMAG_OFF;

#pragma unroll
    for (int f = 0; f < Fn; ++f) {
        U64 u;
        u.u = ar[f];
        float2 vr2;
        vr2.x = fmaxf(u.f.x * sc, 0.0f);
        vr2.y = fmaxf(u.f.y * sc, 0.0f);
        __stcs(reinterpret_cast<float2*>(o_real + (size_t)f * LM), vr2);

        u.u = ai[f];
        float2 vi2;
        vi2.x = u.f.x * sc;
        vi2.y = u.f.y * sc;
        __stcs(reinterpret_cast<float2*>(o_imag + (size_t)f * LM), vi2);
    }
}

extern "C" void kernel_launch(void* const* d_in, const int* in_sizes, int n_in,
                              void* d_out, int out_size) {
    const float* x_real = (const float*)d_in[0];
    const float* x_imag = (const float*)d_in[1];
    const float* w_real = (const float*)d_in[2];
    const float* w_imag = (const float*)d_in[3];
    float* out = (float*)d_out;

    sphere_v10_kernel<<<Bn * Ln, 128>>>(x_real, x_imag, w_real, w_imag, out);
}